// round 1
// baseline (speedup 1.0000x reference)
#include <cuda_runtime.h>
#include <math.h>

#define BSZ   2
#define SEQ   2048
#define HID   4096
#define NH    32
#define DH    128
#define MROWS (BSZ * SEQ)

// ---------------- scratch (static device globals; no allocation allowed) ----
__device__ float g_Q[(size_t)MROWS * HID];
__device__ float g_K[(size_t)MROWS * HID];
__device__ float g_V[(size_t)MROWS * HID];
__device__ float g_AO[(size_t)MROWS * HID];

// ---------------------------------------------------------------------------
// SGEMM  C[m,n] = sum_k A[m,k] * W[n,k]   (NT, all row-major, M=N=K=4096)
// 128x128 block tile, BK=8, 256 threads, 8x8 per-thread micro tile.
// sel_a: 0 -> external A, 1 -> g_AO.  sel_c: 0..2 -> g_Q/g_K/g_V, 3 -> external C.
// ---------------------------------------------------------------------------
__global__ __launch_bounds__(256) void sgemm_nt(int sel_a,
                                                const float* __restrict__ Aext,
                                                const float* __restrict__ W,
                                                int sel_c,
                                                float* __restrict__ Cext)
{
    const int Kdim = HID, Ndim = HID;
    const float* A = (sel_a == 0) ? Aext : g_AO;
    float* C;
    switch (sel_c) {
        case 0:  C = g_Q;  break;
        case 1:  C = g_K;  break;
        case 2:  C = g_V;  break;
        default: C = Cext; break;
    }

    __shared__ float As[8][128];
    __shared__ float Bs[8][128];

    const int t  = threadIdx.x;
    const int tx = t & 15;        // 0..15 -> column group
    const int ty = t >> 4;        // 0..15 -> row group
    const int bm = blockIdx.y * 128;
    const int bn = blockIdx.x * 128;

    const int lm = t >> 1;        // 0..127 row within tile
    const int lk = (t & 1) * 4;   // 0 or 4

    const float* Ap = A + (size_t)(bm + lm) * Kdim + lk;
    const float* Bp = W + (size_t)(bn + lm) * Kdim + lk;

    float acc[8][8];
#pragma unroll
    for (int i = 0; i < 8; ++i)
#pragma unroll
        for (int j = 0; j < 8; ++j) acc[i][j] = 0.0f;

    for (int k0 = 0; k0 < Kdim; k0 += 8) {
        float4 av = *(const float4*)(Ap + k0);
        float4 bv = *(const float4*)(Bp + k0);
        __syncthreads();
        As[lk + 0][lm] = av.x; As[lk + 1][lm] = av.y;
        As[lk + 2][lm] = av.z; As[lk + 3][lm] = av.w;
        Bs[lk + 0][lm] = bv.x; Bs[lk + 1][lm] = bv.y;
        Bs[lk + 2][lm] = bv.z; Bs[lk + 3][lm] = bv.w;
        __syncthreads();
#pragma unroll
        for (int kk = 0; kk < 8; ++kk) {
            float a[8], b[8];
            *(float4*)(a)     = *(const float4*)(&As[kk][ty * 8]);
            *(float4*)(a + 4) = *(const float4*)(&As[kk][ty * 8 + 4]);
            *(float4*)(b)     = *(const float4*)(&Bs[kk][tx * 8]);
            *(float4*)(b + 4) = *(const float4*)(&Bs[kk][tx * 8 + 4]);
#pragma unroll
            for (int i = 0; i < 8; ++i)
#pragma unroll
                for (int j = 0; j < 8; ++j)
                    acc[i][j] = fmaf(a[i], b[j], acc[i][j]);
        }
    }

#pragma unroll
    for (int i = 0; i < 8; ++i) {
        float* Cp = C + (size_t)(bm + ty * 8 + i) * Ndim + bn + tx * 8;
        *(float4*)(Cp)     = make_float4(acc[i][0], acc[i][1], acc[i][2], acc[i][3]);
        *(float4*)(Cp + 4) = make_float4(acc[i][4], acc[i][5], acc[i][6], acc[i][7]);
    }
}

// ---------------------------------------------------------------------------
// RoPE in-place on g_Q (blockIdx.y==0) and g_K (blockIdx.y==1).
// One block per row (b*S+s); 256 threads, 8 (h,j) pairs each.
// ---------------------------------------------------------------------------
__global__ __launch_bounds__(256) void rope_kernel(const int* __restrict__ pos_ids)
{
    __shared__ float s_inv[64];
    if (threadIdx.x < 64) {
        // inv_freq[j] = 10000^(-2j/128), computed in double for accuracy
        s_inv[threadIdx.x] =
            (float)exp(-(double)threadIdx.x * (2.0 / (double)DH) * log(10000.0));
    }
    __syncthreads();

    const int row = blockIdx.x;          // 0..MROWS-1
    const int s   = row & (SEQ - 1);
    const float p = (float)pos_ids[s];
    float* base = (blockIdx.y == 0 ? g_Q : g_K) + (size_t)row * HID;

#pragma unroll
    for (int it = 0; it < 8; ++it) {
        int pi = threadIdx.x + it * 256;   // 0..2047
        int h  = pi >> 6;
        int j  = pi & 63;
        float ang = p * s_inv[j];
        float sn, cs;
        sincosf(ang, &sn, &cs);
        int col  = h * DH + j;
        float x1 = base[col];
        float x2 = base[col + 64];
        base[col]      = x1 * cs - x2 * sn;
        base[col + 64] = x2 * cs + x1 * sn;
    }
}

// ---------------------------------------------------------------------------
// Causal flash attention. grid = (S/128, NH, BSZ), 512 threads.
// Q tile 128 rows, K/V tiles 64 rows, online softmax, result -> g_AO in
// [B,S,H] layout (head h occupies columns h*128..h*128+127).
// Dynamic smem: Qs^T[128][132] + Ks^T[128][68] + Vs[64][132] + Ps[128][68]
// ---------------------------------------------------------------------------
#define QS_STR 132
#define KS_STR 68
#define VS_STR 132
#define PS_STR 68
#define ATTN_SMEM ((128 * QS_STR + 128 * KS_STR + 64 * VS_STR + 128 * PS_STR) * 4)

__global__ __launch_bounds__(512, 1) void flash_attn()
{
    extern __shared__ float sm[];
    float* Qs = sm;                              // Qs[d*QS_STR + r], pre-scaled
    float* Ks = Qs + 128 * QS_STR;               // Ks[d*KS_STR + c]
    float* Vs = Ks + 128 * KS_STR;               // Vs[c*VS_STR + d]
    float* Ps = Vs + 64 * VS_STR;                // Ps[r*PS_STR + c]

    const int qt = blockIdx.x, h = blockIdx.y, b = blockIdx.z;
    const int qbase = qt * 128;
    const int t  = threadIdx.x;
    const int tx = t & 15;         // 0..15
    const int ty = t >> 4;         // 0..31
    const int r0 = ty * 4;         // owned S rows
    const int c0 = tx * 4;         // owned S cols
    const int oc = tx * 8;         // owned O cols
    const float scale = 0.08838834764831845f;    // 1/sqrt(128)

    // ---- load Q tile (scaled), transposed into smem ----
#pragma unroll
    for (int it = 0; it < 8; ++it) {
        int q4 = t + it * 512;         // 0..4095 float4s
        int r  = q4 >> 5;              // 0..127
        int d4 = (q4 & 31) * 4;
        float4 v = *(const float4*)(g_Q + (size_t)(b * SEQ + qbase + r) * HID
                                        + h * DH + d4);
        Qs[(d4 + 0) * QS_STR + r] = v.x * scale;
        Qs[(d4 + 1) * QS_STR + r] = v.y * scale;
        Qs[(d4 + 2) * QS_STR + r] = v.z * scale;
        Qs[(d4 + 3) * QS_STR + r] = v.w * scale;
    }

    float m[4], l[4], o[4][8];
#pragma unroll
    for (int i = 0; i < 4; ++i) {
        m[i] = -1e30f; l[i] = 0.0f;
#pragma unroll
        for (int j = 0; j < 8; ++j) o[i][j] = 0.0f;
    }

    const int nkt = (qbase + 128) / 64;
    for (int kt = 0; kt < nkt; ++kt) {
        const int kbase = kt * 64;
        __syncthreads();   // prev PV done + Q loaded before overwriting tiles
        // ---- load K (transposed) and V tiles ----
#pragma unroll
        for (int it = 0; it < 4; ++it) {
            int q4 = t + it * 512;     // 0..2047 float4s
            int c  = q4 >> 5;          // 0..63
            int d4 = (q4 & 31) * 4;
            size_t go = (size_t)(b * SEQ + kbase + c) * HID + h * DH + d4;
            float4 kv = *(const float4*)(g_K + go);
            Ks[(d4 + 0) * KS_STR + c] = kv.x;
            Ks[(d4 + 1) * KS_STR + c] = kv.y;
            Ks[(d4 + 2) * KS_STR + c] = kv.z;
            Ks[(d4 + 3) * KS_STR + c] = kv.w;
            float4 vv = *(const float4*)(g_V + go);
            *(float4*)(&Vs[c * VS_STR + d4]) = vv;
        }
        __syncthreads();

        // ---- S = (Q*scale) K^T for this tile: 4x4 per thread ----
        float s[4][4];
#pragma unroll
        for (int i = 0; i < 4; ++i)
#pragma unroll
            for (int j = 0; j < 4; ++j) s[i][j] = 0.0f;

#pragma unroll 4
        for (int d = 0; d < 128; ++d) {
            float a[4], bb[4];
            *(float4*)a  = *(const float4*)(&Qs[d * QS_STR + r0]);
            *(float4*)bb = *(const float4*)(&Ks[d * KS_STR + c0]);
#pragma unroll
            for (int i = 0; i < 4; ++i)
#pragma unroll
                for (int j = 0; j < 4; ++j)
                    s[i][j] = fmaf(a[i], bb[j], s[i][j]);
        }

        // ---- causal mask (only diagonal tiles need it) ----
        if (kbase + 63 > qbase) {
#pragma unroll
            for (int i = 0; i < 4; ++i)
#pragma unroll
                for (int j = 0; j < 4; ++j)
                    if (kbase + c0 + j > qbase + r0 + i) s[i][j] = -1e30f;
        }

        // ---- online softmax (row stats shared by the 16 lanes of same ty) ----
#pragma unroll
        for (int i = 0; i < 4; ++i) {
            float mi = fmaxf(fmaxf(s[i][0], s[i][1]), fmaxf(s[i][2], s[i][3]));
#pragma unroll
            for (int off = 8; off > 0; off >>= 1)
                mi = fmaxf(mi, __shfl_xor_sync(0xffffffffu, mi, off));
            float mnew  = fmaxf(m[i], mi);
            float alpha = __expf(m[i] - mnew);
            float p0 = __expf(s[i][0] - mnew);
            float p1 = __expf(s[i][1] - mnew);
            float p2 = __expf(s[i][2] - mnew);
            float p3 = __expf(s[i][3] - mnew);
            float rs = p0 + p1 + p2 + p3;
#pragma unroll
            for (int off = 8; off > 0; off >>= 1)
                rs += __shfl_xor_sync(0xffffffffu, rs, off);
            l[i] = l[i] * alpha + rs;
            m[i] = mnew;
            *(float4*)(&Ps[(r0 + i) * PS_STR + c0]) = make_float4(p0, p1, p2, p3);
#pragma unroll
            for (int j = 0; j < 8; ++j) o[i][j] *= alpha;
        }
        __syncwarp();   // P rows r0..r0+3 are produced within this warp

        // ---- O += P V ----
#pragma unroll 2
        for (int k = 0; k < 64; ++k) {
            float v[8];
            *(float4*)(v)     = *(const float4*)(&Vs[k * VS_STR + oc]);
            *(float4*)(v + 4) = *(const float4*)(&Vs[k * VS_STR + oc + 4]);
            float pr0 = Ps[(r0 + 0) * PS_STR + k];
            float pr1 = Ps[(r0 + 1) * PS_STR + k];
            float pr2 = Ps[(r0 + 2) * PS_STR + k];
            float pr3 = Ps[(r0 + 3) * PS_STR + k];
#pragma unroll
            for (int j = 0; j < 8; ++j) {
                o[0][j] = fmaf(pr0, v[j], o[0][j]);
                o[1][j] = fmaf(pr1, v[j], o[1][j]);
                o[2][j] = fmaf(pr2, v[j], o[2][j]);
                o[3][j] = fmaf(pr3, v[j], o[3][j]);
            }
        }
    }

    // ---- normalize and write to g_AO in [B,S,H] layout ----
#pragma unroll
    for (int i = 0; i < 4; ++i) {
        float inv = 1.0f / l[i];
        float* Op = g_AO + (size_t)(b * SEQ + qbase + r0 + i) * HID + h * DH + oc;
        *(float4*)(Op)     = make_float4(o[i][0] * inv, o[i][1] * inv,
                                         o[i][2] * inv, o[i][3] * inv);
        *(float4*)(Op + 4) = make_float4(o[i][4] * inv, o[i][5] * inv,
                                         o[i][6] * inv, o[i][7] * inv);
    }
}

// ---------------------------------------------------------------------------
extern "C" void kernel_launch(void* const* d_in, const int* in_sizes, int n_in,
                              void* d_out, int out_size)
{
    const float* X  = (const float*)d_in[0];  // hidden_states [B,S,H]
    const float* Wq = (const float*)d_in[1];
    const float* Wk = (const float*)d_in[2];
    const float* Wv = (const float*)d_in[3];
    const float* Wo = (const float*)d_in[4];
    // d_in[5] = attn_mask (pure causal; implemented directly)
    const int*  pos = (const int*)d_in[6];    // position_ids [1,S]
    float* out = (float*)d_out;

    dim3 gemm_grid(HID / 128, MROWS / 128);

    sgemm_nt<<<gemm_grid, 256>>>(0, X, Wq, 0, nullptr);
    sgemm_nt<<<gemm_grid, 256>>>(0, X, Wk, 1, nullptr);
    sgemm_nt<<<gemm_grid, 256>>>(0, X, Wv, 2, nullptr);

    rope_kernel<<<dim3(MROWS, 2), 256>>>(pos);

    cudaFuncSetAttribute(flash_attn,
                         cudaFuncAttributeMaxDynamicSharedMemorySize, ATTN_SMEM);
    flash_attn<<<dim3(SEQ / 128, NH, BSZ), 512, ATTN_SMEM>>>();

    sgemm_nt<<<gemm_grid, 256>>>(1, nullptr, Wo, 3, out);
}

// round 5
// speedup vs baseline: 2.4883x; 2.4883x over previous
#include <cuda_runtime.h>
#include <cuda_bf16.h>
#include <math.h>
#include <stdint.h>

typedef __nv_bfloat16 bf16;

#define BSZ   2
#define SEQ   2048
#define HID   4096
#define NH    32
#define DH    128
#define MROWS (BSZ * SEQ)

// ---------------- scratch (static device globals; no allocation allowed) ----
__device__ float g_Q[(size_t)MROWS * HID];
__device__ float g_K[(size_t)MROWS * HID];
__device__ float g_V[(size_t)MROWS * HID];
__device__ float g_AO[(size_t)MROWS * HID];

// bf16 hi/lo splits
__device__ bf16 g_Xh[(size_t)MROWS * HID],  g_Xl[(size_t)MROWS * HID];
__device__ bf16 g_AOh[(size_t)MROWS * HID], g_AOl[(size_t)MROWS * HID];
__device__ bf16 g_Wqh[(size_t)HID * HID], g_Wql[(size_t)HID * HID];
__device__ bf16 g_Wkh[(size_t)HID * HID], g_Wkl[(size_t)HID * HID];
__device__ bf16 g_Wvh[(size_t)HID * HID], g_Wvl[(size_t)HID * HID];
__device__ bf16 g_Woh[(size_t)HID * HID], g_Wol[(size_t)HID * HID];

// ---------------- PTX helpers (all sm_80-class; no 'a'-gated features) -----
__device__ __forceinline__ uint32_t cvta_s(const void* p) {
    return (uint32_t)__cvta_generic_to_shared(p);
}
#define CP_ASYNC16(saddr, gptr) \
    asm volatile("cp.async.cg.shared.global [%0], [%1], 16;" \
                 :: "r"(saddr), "l"(gptr))
#define CP_COMMIT() asm volatile("cp.async.commit_group;")
#define CP_WAIT0()  asm volatile("cp.async.wait_group 0;")

#define LDSM4(r, addr) \
    asm volatile("ldmatrix.sync.aligned.m8n8.x4.shared.b16 {%0,%1,%2,%3}, [%4];" \
                 : "=r"((r)[0]), "=r"((r)[1]), "=r"((r)[2]), "=r"((r)[3]) \
                 : "r"(addr))

#define MMA16816(d, a, b) \
    asm volatile("mma.sync.aligned.m16n8k16.row.col.f32.bf16.bf16.f32 " \
                 "{%0,%1,%2,%3}, {%4,%5,%6,%7}, {%8,%9}, {%0,%1,%2,%3};" \
                 : "+f"((d)[0]), "+f"((d)[1]), "+f"((d)[2]), "+f"((d)[3]) \
                 : "r"((a)[0]), "r"((a)[1]), "r"((a)[2]), "r"((a)[3]), \
                   "r"((b)[0]), "r"((b)[1]))

// =========================================================================
// split-to-bf16 conversion:  hi = bf16(x), lo = bf16(x - hi)
// dst_sel: 0=X 1=Wq 2=Wk 3=Wv 4=Wo 5=AO(src from g_AO)
// =========================================================================
__global__ __launch_bounds__(256) void convert_split(const float* __restrict__ src,
                                                     int dst_sel) {
    bf16 *hi, *lo;
    switch (dst_sel) {
        case 0: hi = g_Xh;  lo = g_Xl;  break;
        case 1: hi = g_Wqh; lo = g_Wql; break;
        case 2: hi = g_Wkh; lo = g_Wkl; break;
        case 3: hi = g_Wvh; lo = g_Wvl; break;
        case 4: hi = g_Woh; lo = g_Wol; break;
        default: hi = g_AOh; lo = g_AOl; src = g_AO; break;
    }
    size_t i = (size_t)blockIdx.x * blockDim.x + threadIdx.x;  // float4 index
    float4 v = ((const float4*)src)[i];
    bf16 h0 = __float2bfloat16(v.x), h1 = __float2bfloat16(v.y);
    bf16 h2 = __float2bfloat16(v.z), h3 = __float2bfloat16(v.w);
    bf16 l0 = __float2bfloat16(v.x - __bfloat162float(h0));
    bf16 l1 = __float2bfloat16(v.y - __bfloat162float(h1));
    bf16 l2 = __float2bfloat16(v.z - __bfloat162float(h2));
    bf16 l3 = __float2bfloat16(v.w - __bfloat162float(h3));
    __nv_bfloat162 hp0 = {h0, h1}, hp1 = {h2, h3};
    __nv_bfloat162 lp0 = {l0, l1}, lp1 = {l2, l3};
    ((__nv_bfloat162*)hi)[i * 2]     = hp0;
    ((__nv_bfloat162*)hi)[i * 2 + 1] = hp1;
    ((__nv_bfloat162*)lo)[i * 2]     = lp0;
    ((__nv_bfloat162*)lo)[i * 2 + 1] = lp1;
}

// =========================================================================
// mma.sync bf16 3-term GEMM:  C[m,n] = sum_k A[m,k] * W[n,k]
// CTA tile 128x128, K-chunk 64, 256 threads (8 warps, 2x4), double buffered
// cp.async SMEM. Tiles per buffer: Ah, Al, Bh, Bl each 128x64 bf16 (16 KB).
// mode 0: A = X splits, W/C by blockIdx.z (Q/K/V).  mode 1: AO x Wo -> Cext.
// =========================================================================
#define TILE_B   16384          // one 128x64 bf16 tile
#define BUF_B    65536          // 4 tiles
#define GEMM_SMEM (2 * BUF_B)
#define NCHUNK   64

__global__ __launch_bounds__(256, 1) void gemm_mma3(float* __restrict__ Cext,
                                                    int mode) {
    extern __shared__ char dsm[];
    const uint32_t sb = cvta_s(dsm);

    const bf16 *Ah, *Al, *Wh, *Wl;
    float* C;
    if (mode == 0) {
        Ah = g_Xh; Al = g_Xl;
        int z = blockIdx.z;
        Wh = (z == 0) ? g_Wqh : (z == 1) ? g_Wkh : g_Wvh;
        Wl = (z == 0) ? g_Wql : (z == 1) ? g_Wkl : g_Wvl;
        C  = (z == 0) ? g_Q   : (z == 1) ? g_K   : g_V;
    } else {
        Ah = g_AOh; Al = g_AOl; Wh = g_Woh; Wl = g_Wol; C = Cext;
    }

    const int t    = threadIdx.x;
    const int lane = t & 31;
    const int wid  = t >> 5;
    const int wm   = wid >> 2;          // 0..1 -> m offset wm*64
    const int wn   = wid & 3;           // 0..3 -> n offset wn*32
    const int bm   = blockIdx.y * 128;
    const int bn   = blockIdx.x * 128;

    // ---- per-lane ldmatrix row byte-offsets (within a tile) ----
    const int lxor = lane & 7;
    uint32_t aRow[4], bRow[2];
#pragma unroll
    for (int mt = 0; mt < 4; ++mt)
        aRow[mt] = (uint32_t)((wm * 64 + mt * 16 + (lane & 15)) * 128);
#pragma unroll
    for (int np = 0; np < 2; ++np)
        bRow[np] = (uint32_t)((wn * 32 + np * 16 + (lane & 7) + ((lane & 16) >> 1)) * 128);
    const int uA = lane >> 4;           // 0/1
    const int uB = (lane >> 3) & 1;     // 0/1

    // ---- loader: chunk k0 -> buffer buf (cp.async) ----
    auto load_chunk = [&](int buf, int k0) {
        const bf16* srcs[4] = {Ah, Al, Wh, Wl};
#pragma unroll
        for (int tile = 0; tile < 4; ++tile) {
            const int rowbase = (tile < 2) ? bm : bn;
            const bf16* src = srcs[tile];
#pragma unroll
            for (int i = 0; i < 4; ++i) {
                int idx = t + i * 256;          // 0..1023
                int r = idx >> 3, u = idx & 7;
                uint32_t soff = (uint32_t)(buf * BUF_B + tile * TILE_B
                                           + r * 128 + ((u ^ (r & 7)) << 4));
                const bf16* g = src + (size_t)(rowbase + r) * HID + k0 + u * 8;
                CP_ASYNC16(sb + soff, g);
            }
        }
    };

    float acc[4][4][4];
#pragma unroll
    for (int mt = 0; mt < 4; ++mt)
#pragma unroll
        for (int nt = 0; nt < 4; ++nt)
#pragma unroll
            for (int j = 0; j < 4; ++j) acc[mt][nt][j] = 0.0f;

    load_chunk(0, 0);
    CP_COMMIT();
    CP_WAIT0();
    __syncthreads();

    for (int c = 0; c < NCHUNK; ++c) {
        const int buf = c & 1;
        if (c + 1 < NCHUNK) {
            load_chunk(buf ^ 1, (c + 1) * 64);
            CP_COMMIT();
        }

        const uint32_t base = sb + buf * BUF_B;
#pragma unroll
        for (int ks = 0; ks < 4; ++ks) {
            const uint32_t offA = (uint32_t)((((2 * ks + uA) ^ lxor)) << 4);
            const uint32_t offB = (uint32_t)((((2 * ks + uB) ^ lxor)) << 4);
            uint32_t ah[4][4], al[4][4], bh[2][4], bl[2][4];
#pragma unroll
            for (int mt = 0; mt < 4; ++mt) {
                LDSM4(ah[mt], base + 0 * TILE_B + aRow[mt] + offA);
                LDSM4(al[mt], base + 1 * TILE_B + aRow[mt] + offA);
            }
#pragma unroll
            for (int np = 0; np < 2; ++np) {
                LDSM4(bh[np], base + 2 * TILE_B + bRow[np] + offB);
                LDSM4(bl[np], base + 3 * TILE_B + bRow[np] + offB);
            }
#pragma unroll
            for (int mt = 0; mt < 4; ++mt)
#pragma unroll
                for (int nt = 0; nt < 4; ++nt) {
                    const uint32_t* bhp = &bh[nt >> 1][(nt & 1) * 2];
                    const uint32_t* blp = &bl[nt >> 1][(nt & 1) * 2];
                    MMA16816(acc[mt][nt], ah[mt], bhp);
                    MMA16816(acc[mt][nt], ah[mt], blp);
                    MMA16816(acc[mt][nt], al[mt], bhp);
                }
        }

        if (c + 1 < NCHUNK) {
            CP_WAIT0();
            __syncthreads();
        }
    }

    // ---- epilogue: fragment -> C ----
    const int g  = lane >> 2;        // 0..7
    const int tq = lane & 3;         // 0..3
#pragma unroll
    for (int mt = 0; mt < 4; ++mt) {
        const int row0 = bm + wm * 64 + mt * 16 + g;
#pragma unroll
        for (int nt = 0; nt < 4; ++nt) {
            const int col = bn + wn * 32 + nt * 8 + tq * 2;
            *(float2*)(C + (size_t)row0 * HID + col) =
                make_float2(acc[mt][nt][0], acc[mt][nt][1]);
            *(float2*)(C + (size_t)(row0 + 8) * HID + col) =
                make_float2(acc[mt][nt][2], acc[mt][nt][3]);
        }
    }
}

// =========================================================================
// RoPE in-place on g_Q (blockIdx.y==0) and g_K (blockIdx.y==1).
// =========================================================================
__global__ __launch_bounds__(256) void rope_kernel(const int* __restrict__ pos_ids)
{
    __shared__ float s_inv[64];
    if (threadIdx.x < 64) {
        s_inv[threadIdx.x] =
            (float)exp(-(double)threadIdx.x * (2.0 / (double)DH) * log(10000.0));
    }
    __syncthreads();

    const int row = blockIdx.x;
    const int s   = row & (SEQ - 1);
    const float p = (float)pos_ids[s];
    float* base = (blockIdx.y == 0 ? g_Q : g_K) + (size_t)row * HID;

#pragma unroll
    for (int it = 0; it < 8; ++it) {
        int pi = threadIdx.x + it * 256;
        int h  = pi >> 6;
        int j  = pi & 63;
        float ang = p * s_inv[j];
        float sn, cs;
        sincosf(ang, &sn, &cs);
        int col  = h * DH + j;
        float x1 = base[col];
        float x2 = base[col + 64];
        base[col]      = x1 * cs - x2 * sn;
        base[col + 64] = x2 * cs + x1 * sn;
    }
}

// =========================================================================
// Causal flash attention (fp32). grid = (S/128, NH, BSZ), 512 threads.
// =========================================================================
#define QS_STR 132
#define KS_STR 68
#define VS_STR 132
#define PS_STR 68
#define ATTN_SMEM ((128 * QS_STR + 128 * KS_STR + 64 * VS_STR + 128 * PS_STR) * 4)

__global__ __launch_bounds__(512, 1) void flash_attn()
{
    extern __shared__ float sm[];
    float* Qs = sm;
    float* Ks = Qs + 128 * QS_STR;
    float* Vs = Ks + 128 * KS_STR;
    float* Ps = Vs + 64 * VS_STR;

    const int qt = blockIdx.x, h = blockIdx.y, b = blockIdx.z;
    const int qbase = qt * 128;
    const int t  = threadIdx.x;
    const int tx = t & 15;
    const int ty = t >> 4;
    const int r0 = ty * 4;
    const int c0 = tx * 4;
    const int oc = tx * 8;
    const float scale = 0.08838834764831845f;

#pragma unroll
    for (int it = 0; it < 8; ++it) {
        int q4 = t + it * 512;
        int r  = q4 >> 5;
        int d4 = (q4 & 31) * 4;
        float4 v = *(const float4*)(g_Q + (size_t)(b * SEQ + qbase + r) * HID
                                        + h * DH + d4);
        Qs[(d4 + 0) * QS_STR + r] = v.x * scale;
        Qs[(d4 + 1) * QS_STR + r] = v.y * scale;
        Qs[(d4 + 2) * QS_STR + r] = v.z * scale;
        Qs[(d4 + 3) * QS_STR + r] = v.w * scale;
    }

    float m[4], l[4], o[4][8];
#pragma unroll
    for (int i = 0; i < 4; ++i) {
        m[i] = -1e30f; l[i] = 0.0f;
#pragma unroll
        for (int j = 0; j < 8; ++j) o[i][j] = 0.0f;
    }

    const int nkt = (qbase + 128) / 64;
    for (int kt = 0; kt < nkt; ++kt) {
        const int kbase = kt * 64;
        __syncthreads();
#pragma unroll
        for (int it = 0; it < 4; ++it) {
            int q4 = t + it * 512;
            int c  = q4 >> 5;
            int d4 = (q4 & 31) * 4;
            size_t go = (size_t)(b * SEQ + kbase + c) * HID + h * DH + d4;
            float4 kv = *(const float4*)(g_K + go);
            Ks[(d4 + 0) * KS_STR + c] = kv.x;
            Ks[(d4 + 1) * KS_STR + c] = kv.y;
            Ks[(d4 + 2) * KS_STR + c] = kv.z;
            Ks[(d4 + 3) * KS_STR + c] = kv.w;
            float4 vv = *(const float4*)(g_V + go);
            *(float4*)(&Vs[c * VS_STR + d4]) = vv;
        }
        __syncthreads();

        float s[4][4];
#pragma unroll
        for (int i = 0; i < 4; ++i)
#pragma unroll
            for (int j = 0; j < 4; ++j) s[i][j] = 0.0f;

#pragma unroll 4
        for (int d = 0; d < 128; ++d) {
            float a[4], bb[4];
            *(float4*)a  = *(const float4*)(&Qs[d * QS_STR + r0]);
            *(float4*)bb = *(const float4*)(&Ks[d * KS_STR + c0]);
#pragma unroll
            for (int i = 0; i < 4; ++i)
#pragma unroll
                for (int j = 0; j < 4; ++j)
                    s[i][j] = fmaf(a[i], bb[j], s[i][j]);
        }

        if (kbase + 63 > qbase) {
#pragma unroll
            for (int i = 0; i < 4; ++i)
#pragma unroll
                for (int j = 0; j < 4; ++j)
                    if (kbase + c0 + j > qbase + r0 + i) s[i][j] = -1e30f;
        }

#pragma unroll
        for (int i = 0; i < 4; ++i) {
            float mi = fmaxf(fmaxf(s[i][0], s[i][1]), fmaxf(s[i][2], s[i][3]));
#pragma unroll
            for (int off = 8; off > 0; off >>= 1)
                mi = fmaxf(mi, __shfl_xor_sync(0xffffffffu, mi, off));
            float mnew  = fmaxf(m[i], mi);
            float alpha = __expf(m[i] - mnew);
            float p0 = __expf(s[i][0] - mnew);
            float p1 = __expf(s[i][1] - mnew);
            float p2 = __expf(s[i][2] - mnew);
            float p3 = __expf(s[i][3] - mnew);
            float rs = p0 + p1 + p2 + p3;
#pragma unroll
            for (int off = 8; off > 0; off >>= 1)
                rs += __shfl_xor_sync(0xffffffffu, rs, off);
            l[i] = l[i] * alpha + rs;
            m[i] = mnew;
            *(float4*)(&Ps[(r0 + i) * PS_STR + c0]) = make_float4(p0, p1, p2, p3);
#pragma unroll
            for (int j = 0; j < 8; ++j) o[i][j] *= alpha;
        }
        __syncwarp();

#pragma unroll 2
        for (int k = 0; k < 64; ++k) {
            float v[8];
            *(float4*)(v)     = *(const float4*)(&Vs[k * VS_STR + oc]);
            *(float4*)(v + 4) = *(const float4*)(&Vs[k * VS_STR + oc + 4]);
            float pr0 = Ps[(r0 + 0) * PS_STR + k];
            float pr1 = Ps[(r0 + 1) * PS_STR + k];
            float pr2 = Ps[(r0 + 2) * PS_STR + k];
            float pr3 = Ps[(r0 + 3) * PS_STR + k];
#pragma unroll
            for (int j = 0; j < 8; ++j) {
                o[0][j] = fmaf(pr0, v[j], o[0][j]);
                o[1][j] = fmaf(pr1, v[j], o[1][j]);
                o[2][j] = fmaf(pr2, v[j], o[2][j]);
                o[3][j] = fmaf(pr3, v[j], o[3][j]);
            }
        }
    }

#pragma unroll
    for (int i = 0; i < 4; ++i) {
        float inv = 1.0f / l[i];
        float* Op = g_AO + (size_t)(b * SEQ + qbase + r0 + i) * HID + h * DH + oc;
        *(float4*)(Op)     = make_float4(o[i][0] * inv, o[i][1] * inv,
                                         o[i][2] * inv, o[i][3] * inv);
        *(float4*)(Op + 4) = make_float4(o[i][4] * inv, o[i][5] * inv,
                                         o[i][6] * inv, o[i][7] * inv);
    }
}

// =========================================================================
extern "C" void kernel_launch(void* const* d_in, const int* in_sizes, int n_in,
                              void* d_out, int out_size)
{
    const float* X  = (const float*)d_in[0];
    const float* Wq = (const float*)d_in[1];
    const float* Wk = (const float*)d_in[2];
    const float* Wv = (const float*)d_in[3];
    const float* Wo = (const float*)d_in[4];
    const int*  pos = (const int*)d_in[6];
    float* out = (float*)d_out;

    const int conv_blocks = (int)(((size_t)HID * HID / 4) / 256);   // 16384

    convert_split<<<conv_blocks, 256>>>(X,  0);
    convert_split<<<conv_blocks, 256>>>(Wq, 1);
    convert_split<<<conv_blocks, 256>>>(Wk, 2);
    convert_split<<<conv_blocks, 256>>>(Wv, 3);
    convert_split<<<conv_blocks, 256>>>(Wo, 4);

    cudaFuncSetAttribute(gemm_mma3,
                         cudaFuncAttributeMaxDynamicSharedMemorySize, GEMM_SMEM);
    gemm_mma3<<<dim3(HID / 128, MROWS / 128, 3), 256, GEMM_SMEM>>>(nullptr, 0);

    rope_kernel<<<dim3(MROWS, 2), 256>>>(pos);

    cudaFuncSetAttribute(flash_attn,
                         cudaFuncAttributeMaxDynamicSharedMemorySize, ATTN_SMEM);
    flash_attn<<<dim3(SEQ / 128, NH, BSZ), 512, ATTN_SMEM>>>();

    convert_split<<<conv_blocks, 256>>>(nullptr, 5);
    gemm_mma3<<<dim3(HID / 128, MROWS / 128, 1), 256, GEMM_SMEM>>>(out, 1);
}

// round 12
// speedup vs baseline: 3.6886x; 1.4824x over previous
#include <cuda_runtime.h>
#include <cuda_bf16.h>
#include <math.h>
#include <stdint.h>

typedef __nv_bfloat16 bf16;

#define BSZ   2
#define SEQ   2048
#define HID   4096
#define NH    32
#define DH    128
#define MROWS (BSZ * SEQ)

// ---------------- scratch (static device globals; no allocation allowed) ----
__device__ float g_Q[(size_t)MROWS * HID];
__device__ float g_K[(size_t)MROWS * HID];
__device__ float g_V[(size_t)MROWS * HID];
__device__ float g_AO[(size_t)MROWS * HID];

// bf16 hi/lo splits
__device__ bf16 g_Xh[(size_t)MROWS * HID],  g_Xl[(size_t)MROWS * HID];
__device__ bf16 g_AOh[(size_t)MROWS * HID], g_AOl[(size_t)MROWS * HID];
__device__ bf16 g_Wqh[(size_t)HID * HID], g_Wql[(size_t)HID * HID];
__device__ bf16 g_Wkh[(size_t)HID * HID], g_Wkl[(size_t)HID * HID];
__device__ bf16 g_Wvh[(size_t)HID * HID], g_Wvl[(size_t)HID * HID];
__device__ bf16 g_Woh[(size_t)HID * HID], g_Wol[(size_t)HID * HID];
// attention operand splits (Q/K roped+scaled; V transposed to [b,h,d,s])
__device__ bf16 g_Qbh[(size_t)MROWS * HID], g_Qbl[(size_t)MROWS * HID];
__device__ bf16 g_Kbh[(size_t)MROWS * HID], g_Kbl[(size_t)MROWS * HID];
__device__ bf16 g_Vth[(size_t)MROWS * HID], g_Vtl[(size_t)MROWS * HID];

// ---------------- PTX helpers (all sm_80-class; no 'a'-gated features) -----
__device__ __forceinline__ uint32_t cvta_s(const void* p) {
    return (uint32_t)__cvta_generic_to_shared(p);
}
#define CP_ASYNC16(saddr, gptr) \
    asm volatile("cp.async.cg.shared.global [%0], [%1], 16;" \
                 :: "r"(saddr), "l"(gptr))
#define CP_COMMIT() asm volatile("cp.async.commit_group;")
#define CP_WAIT0()  asm volatile("cp.async.wait_group 0;")

#define LDSM4(r, addr) \
    asm volatile("ldmatrix.sync.aligned.m8n8.x4.shared.b16 {%0,%1,%2,%3}, [%4];" \
                 : "=r"((r)[0]), "=r"((r)[1]), "=r"((r)[2]), "=r"((r)[3]) \
                 : "r"(addr))

#define MMA16816(d, a, b) \
    asm volatile("mma.sync.aligned.m16n8k16.row.col.f32.bf16.bf16.f32 " \
                 "{%0,%1,%2,%3}, {%4,%5,%6,%7}, {%8,%9}, {%0,%1,%2,%3};" \
                 : "+f"((d)[0]), "+f"((d)[1]), "+f"((d)[2]), "+f"((d)[3]) \
                 : "r"((a)[0]), "r"((a)[1]), "r"((a)[2]), "r"((a)[3]), \
                   "r"((b)[0]), "r"((b)[1]))

__device__ __forceinline__ void split_hl(float a, bf16& h, bf16& l) {
    h = __float2bfloat16(a);
    l = __float2bfloat16(a - __bfloat162float(h));
}
__device__ __forceinline__ void pack_hl(float a, float b,
                                        uint32_t& hi, uint32_t& lo) {
    bf16 ha, la, hb, lb;
    split_hl(a, ha, la);
    split_hl(b, hb, lb);
    __nv_bfloat162 hp; hp.x = ha; hp.y = hb;
    __nv_bfloat162 lp; lp.x = la; lp.y = lb;
    hi = *(uint32_t*)&hp;
    lo = *(uint32_t*)&lp;
}

// =========================================================================
// split-to-bf16 conversion:  hi = bf16(x), lo = bf16(x - hi)
// dst_sel: 0=X 1=Wq 2=Wk 3=Wv 4=Wo 5=AO(src from g_AO)
// =========================================================================
__global__ __launch_bounds__(256) void convert_split(const float* __restrict__ src,
                                                     int dst_sel) {
    bf16 *hi, *lo;
    switch (dst_sel) {
        case 0: hi = g_Xh;  lo = g_Xl;  break;
        case 1: hi = g_Wqh; lo = g_Wql; break;
        case 2: hi = g_Wkh; lo = g_Wkl; break;
        case 3: hi = g_Wvh; lo = g_Wvl; break;
        case 4: hi = g_Woh; lo = g_Wol; break;
        default: hi = g_AOh; lo = g_AOl; src = g_AO; break;
    }
    size_t i = (size_t)blockIdx.x * blockDim.x + threadIdx.x;  // float4 index
    float4 v = ((const float4*)src)[i];
    uint32_t h0, l0, h1, l1;
    pack_hl(v.x, v.y, h0, l0);
    pack_hl(v.z, v.w, h1, l1);
    ((uint32_t*)hi)[i * 2]     = h0;
    ((uint32_t*)hi)[i * 2 + 1] = h1;
    ((uint32_t*)lo)[i * 2]     = l0;
    ((uint32_t*)lo)[i * 2 + 1] = l1;
}

// =========================================================================
// mma.sync bf16 3-term GEMM:  C[m,n] = sum_k A[m,k] * W[n,k]
// (unchanged from round-5 passing kernel)
// =========================================================================
#define TILE_B   16384
#define BUF_B    65536
#define GEMM_SMEM (2 * BUF_B)
#define NCHUNK   64

__global__ __launch_bounds__(256, 1) void gemm_mma3(float* __restrict__ Cext,
                                                    int mode) {
    extern __shared__ char dsm[];
    const uint32_t sb = cvta_s(dsm);

    const bf16 *Ah, *Al, *Wh, *Wl;
    float* C;
    if (mode == 0) {
        Ah = g_Xh; Al = g_Xl;
        int z = blockIdx.z;
        Wh = (z == 0) ? g_Wqh : (z == 1) ? g_Wkh : g_Wvh;
        Wl = (z == 0) ? g_Wql : (z == 1) ? g_Wkl : g_Wvl;
        C  = (z == 0) ? g_Q   : (z == 1) ? g_K   : g_V;
    } else {
        Ah = g_AOh; Al = g_AOl; Wh = g_Woh; Wl = g_Wol; C = Cext;
    }

    const int t    = threadIdx.x;
    const int lane = t & 31;
    const int wid  = t >> 5;
    const int wm   = wid >> 2;
    const int wn   = wid & 3;
    const int bm   = blockIdx.y * 128;
    const int bn   = blockIdx.x * 128;

    const int lxor = lane & 7;
    uint32_t aRow[4], bRow[2];
#pragma unroll
    for (int mt = 0; mt < 4; ++mt)
        aRow[mt] = (uint32_t)((wm * 64 + mt * 16 + (lane & 15)) * 128);
#pragma unroll
    for (int np = 0; np < 2; ++np)
        bRow[np] = (uint32_t)((wn * 32 + np * 16 + (lane & 7) + ((lane & 16) >> 1)) * 128);
    const int uA = lane >> 4;
    const int uB = (lane >> 3) & 1;

    auto load_chunk = [&](int buf, int k0) {
        const bf16* srcs[4] = {Ah, Al, Wh, Wl};
#pragma unroll
        for (int tile = 0; tile < 4; ++tile) {
            const int rowbase = (tile < 2) ? bm : bn;
            const bf16* src = srcs[tile];
#pragma unroll
            for (int i = 0; i < 4; ++i) {
                int idx = t + i * 256;
                int r = idx >> 3, u = idx & 7;
                uint32_t soff = (uint32_t)(buf * BUF_B + tile * TILE_B
                                           + r * 128 + ((u ^ (r & 7)) << 4));
                const bf16* g = src + (size_t)(rowbase + r) * HID + k0 + u * 8;
                CP_ASYNC16(sb + soff, g);
            }
        }
    };

    float acc[4][4][4];
#pragma unroll
    for (int mt = 0; mt < 4; ++mt)
#pragma unroll
        for (int nt = 0; nt < 4; ++nt)
#pragma unroll
            for (int j = 0; j < 4; ++j) acc[mt][nt][j] = 0.0f;

    load_chunk(0, 0);
    CP_COMMIT();
    CP_WAIT0();
    __syncthreads();

    for (int c = 0; c < NCHUNK; ++c) {
        const int buf = c & 1;
        if (c + 1 < NCHUNK) {
            load_chunk(buf ^ 1, (c + 1) * 64);
            CP_COMMIT();
        }

        const uint32_t base = sb + buf * BUF_B;
#pragma unroll
        for (int ks = 0; ks < 4; ++ks) {
            const uint32_t offA = (uint32_t)((((2 * ks + uA) ^ lxor)) << 4);
            const uint32_t offB = (uint32_t)((((2 * ks + uB) ^ lxor)) << 4);
            uint32_t ah[4][4], al[4][4], bh[2][4], bl[2][4];
#pragma unroll
            for (int mt = 0; mt < 4; ++mt) {
                LDSM4(ah[mt], base + 0 * TILE_B + aRow[mt] + offA);
                LDSM4(al[mt], base + 1 * TILE_B + aRow[mt] + offA);
            }
#pragma unroll
            for (int np = 0; np < 2; ++np) {
                LDSM4(bh[np], base + 2 * TILE_B + bRow[np] + offB);
                LDSM4(bl[np], base + 3 * TILE_B + bRow[np] + offB);
            }
#pragma unroll
            for (int mt = 0; mt < 4; ++mt)
#pragma unroll
                for (int nt = 0; nt < 4; ++nt) {
                    const uint32_t* bhp = &bh[nt >> 1][(nt & 1) * 2];
                    const uint32_t* blp = &bl[nt >> 1][(nt & 1) * 2];
                    MMA16816(acc[mt][nt], ah[mt], bhp);
                    MMA16816(acc[mt][nt], ah[mt], blp);
                    MMA16816(acc[mt][nt], al[mt], bhp);
                }
        }

        if (c + 1 < NCHUNK) {
            CP_WAIT0();
            __syncthreads();
        }
    }

    const int g  = lane >> 2;
    const int tq = lane & 3;
#pragma unroll
    for (int mt = 0; mt < 4; ++mt) {
        const int row0 = bm + wm * 64 + mt * 16 + g;
#pragma unroll
        for (int nt = 0; nt < 4; ++nt) {
            const int col = bn + wn * 32 + nt * 8 + tq * 2;
            *(float2*)(C + (size_t)row0 * HID + col) =
                make_float2(acc[mt][nt][0], acc[mt][nt][1]);
            *(float2*)(C + (size_t)(row0 + 8) * HID + col) =
                make_float2(acc[mt][nt][2], acc[mt][nt][3]);
        }
    }
}

// =========================================================================
// RoPE + scale + split:  fp32 g_Q/g_K -> bf16 hi/lo (Q gets 1/sqrt(Dh))
// =========================================================================
__global__ __launch_bounds__(256) void rope_split(const int* __restrict__ pos_ids)
{
    __shared__ float s_inv[64];
    if (threadIdx.x < 64) {
        s_inv[threadIdx.x] =
            (float)exp(-(double)threadIdx.x * (2.0 / (double)DH) * log(10000.0));
    }
    __syncthreads();

    const int row = blockIdx.x;
    const int s   = row & (SEQ - 1);
    const float p = (float)pos_ids[s];
    const bool isQ = (blockIdx.y == 0);
    const float sc = isQ ? 0.08838834764831845f : 1.0f;
    const float* base = (isQ ? g_Q : g_K) + (size_t)row * HID;
    bf16* hi = (isQ ? g_Qbh : g_Kbh) + (size_t)row * HID;
    bf16* lo = (isQ ? g_Qbl : g_Kbl) + (size_t)row * HID;

#pragma unroll
    for (int it = 0; it < 8; ++it) {
        int pi = threadIdx.x + it * 256;
        int h  = pi >> 6;
        int j  = pi & 63;
        float ang = p * s_inv[j];
        float sn, cs;
        sincosf(ang, &sn, &cs);
        int col  = h * DH + j;
        float x1 = base[col];
        float x2 = base[col + 64];
        float y1 = (x1 * cs - x2 * sn) * sc;
        float y2 = (x2 * cs + x1 * sn) * sc;
        bf16 h1, l1, h2, l2;
        split_hl(y1, h1, l1);
        split_hl(y2, h2, l2);
        hi[col] = h1;       lo[col] = l1;
        hi[col + 64] = h2;  lo[col + 64] = l2;
    }
}

// =========================================================================
// V transpose + split:  g_V [b,s,h,d] fp32 -> g_Vth/g_Vtl [b,h,d,s] bf16
// 64x64 tiles via smem.
// =========================================================================
__global__ __launch_bounds__(256) void vsplit_t()
{
    __shared__ float tile[64][65];
    const int s0 = blockIdx.x * 64;
    const int hy = blockIdx.y;            // h*2 + dhalf
    const int h  = hy >> 1;
    const int dh = (hy & 1) * 64;
    const int b  = blockIdx.z;
    const int t  = threadIdx.x;

#pragma unroll
    for (int i = 0; i < 4; ++i) {
        int idx = t + i * 256;            // 0..1023
        int r = idx >> 4, c4 = (idx & 15) * 4;
        float4 v = *(const float4*)(g_V + (size_t)(b * SEQ + s0 + r) * HID
                                        + h * DH + dh + c4);
        tile[r][c4]     = v.x;
        tile[r][c4 + 1] = v.y;
        tile[r][c4 + 2] = v.z;
        tile[r][c4 + 3] = v.w;
    }
    __syncthreads();

#pragma unroll
    for (int i = 0; i < 8; ++i) {
        int idx = t + i * 256;            // 0..2047
        int d  = idx >> 5;
        int s2 = (idx & 31) * 2;
        uint32_t hv, lv;
        pack_hl(tile[s2][d], tile[s2 + 1][d], hv, lv);
        size_t o = ((size_t)((b * NH + h) * DH + dh + d)) * SEQ + s0 + s2;
        *(uint32_t*)(g_Vth + o) = hv;
        *(uint32_t*)(g_Vtl + o) = lv;
    }
}

// =========================================================================
// Causal flash attention on mma.sync bf16x3.
// grid = (SEQ/128, NH, BSZ), 256 threads (8 warps; warp w owns rows w*16..+15).
// Q tile 128x128 (hi+lo = 64KB), per KV buffer: K 64x128 hi/lo + Vt 128x64
// hi/lo = 64KB, double buffered. Total smem 192KB.
// =========================================================================
#define ATQ_B  32768                       // one 128x128 bf16 Q split
#define KV_B   65536                       // one KV buffer (4 x 16KB)
#define ATTN_SMEM (2 * ATQ_B + 2 * KV_B)   // 196608

__global__ __launch_bounds__(256, 1) void flash_attn_mma()
{
    extern __shared__ char sm[];
    const uint32_t sb = cvta_s(sm);
    const int qt = blockIdx.x, h = blockIdx.y, b = blockIdx.z;
    const int qbase = qt * 128;
    const int t = threadIdx.x, lane = t & 31, w = t >> 5;

    // ---- load Q tile (both splits), swizzled 16B chunks ----
    {
        const bf16* srcs[2] = {g_Qbh, g_Qbl};
#pragma unroll
        for (int sp = 0; sp < 2; ++sp) {
            const bf16* src = srcs[sp];
#pragma unroll
            for (int i = 0; i < 8; ++i) {
                int idx = t + i * 256;       // 0..2047
                int r = idx >> 4, u = idx & 15;
                uint32_t sw = (uint32_t)(((u & 7) ^ (r & 7)) | (u & 8));
                const bf16* g = src + (size_t)(b * SEQ + qbase + r) * HID
                                    + h * DH + u * 8;
                CP_ASYNC16(sb + sp * ATQ_B + r * 256 + (sw << 4), g);
            }
        }
    }

    auto load_kv = [&](int buf, int kt) {
        const uint32_t off = 2 * ATQ_B + buf * KV_B;
        const int kbase = kt * 64;
#pragma unroll
        for (int i = 0; i < 4; ++i) {
            int idx = t + i * 256;           // 0..1023
            int r = idx >> 4, u = idx & 15;
            uint32_t sw = (uint32_t)(((u & 7) ^ (r & 7)) | (u & 8));
            size_t gi = (size_t)(b * SEQ + kbase + r) * HID + h * DH + u * 8;
            CP_ASYNC16(sb + off + r * 256 + (sw << 4), g_Kbh + gi);
            CP_ASYNC16(sb + off + 16384 + r * 256 + (sw << 4), g_Kbl + gi);
        }
#pragma unroll
        for (int i = 0; i < 4; ++i) {
            int idx = t + i * 256;           // 0..1023
            int d = idx >> 3, u = idx & 7;
            uint32_t sw = (uint32_t)(u ^ (d & 7));
            size_t gi = (size_t)((b * NH + h) * DH + d) * SEQ + kbase + u * 8;
            CP_ASYNC16(sb + off + 32768 + d * 128 + (sw << 4), g_Vth + gi);
            CP_ASYNC16(sb + off + 49152 + d * 128 + (sw << 4), g_Vtl + gi);
        }
    };

    load_kv(0, 0);
    CP_COMMIT();
    CP_WAIT0();
    __syncthreads();

    float of[16][4];
#pragma unroll
    for (int nt = 0; nt < 16; ++nt)
#pragma unroll
        for (int j = 0; j < 4; ++j) of[nt][j] = 0.0f;
    float m0 = -1e30f, m1 = -1e30f, l0 = 0.0f, l1 = 0.0f;

    const int nkt = 2 * (qt + 1);
    for (int kt = 0; kt < nkt; ++kt) {
        const int buf = kt & 1;
        if (kt + 1 < nkt) {
            load_kv(buf ^ 1, kt + 1);
            CP_COMMIT();
        }
        const uint32_t kb = sb + 2 * ATQ_B + buf * KV_B;

        // ---- S = Q K^T  (128x64 tile; this warp: 16x64) ----
        float s[8][4];
#pragma unroll
        for (int nt = 0; nt < 8; ++nt)
#pragma unroll
            for (int j = 0; j < 4; ++j) s[nt][j] = 0.0f;

#pragma unroll
        for (int ks = 0; ks < 8; ++ks) {
            uint32_t aH[4], aL[4];
            {
                int r = w * 16 + (lane & 15);
                int c = 2 * ks + (lane >> 4);
                uint32_t sw = (uint32_t)(((c & 7) ^ (r & 7)) | (c & 8));
                uint32_t ad = sb + r * 256 + (sw << 4);
                LDSM4(aH, ad);
                LDSM4(aL, ad + ATQ_B);
            }
#pragma unroll
            for (int np = 0; np < 4; ++np) {
                uint32_t bH[4], bL[4];
                int rr = np * 16 + (lane & 7) + ((lane >> 4) << 3);
                int c  = 2 * ks + ((lane >> 3) & 1);
                uint32_t sw = (uint32_t)(((c & 7) ^ (rr & 7)) | (c & 8));
                uint32_t ad = kb + rr * 256 + (sw << 4);
                LDSM4(bH, ad);
                LDSM4(bL, ad + 16384);
#pragma unroll
                for (int half = 0; half < 2; ++half) {
                    float* acc = s[np * 2 + half];
                    MMA16816(acc, aH, &bH[half * 2]);
                    MMA16816(acc, aH, &bL[half * 2]);
                    MMA16816(acc, aL, &bH[half * 2]);
                }
            }
        }

        // ---- causal mask ----
        const int kbase = kt * 64;
        const int r1g = qbase + w * 16 + (lane >> 2);
        if (kbase + 63 > r1g) {
            const int r2g = r1g + 8;
#pragma unroll
            for (int nt = 0; nt < 8; ++nt) {
                int cg = kbase + nt * 8 + 2 * (lane & 3);
                if (cg > r1g)     s[nt][0] = -1e30f;
                if (cg + 1 > r1g) s[nt][1] = -1e30f;
                if (cg > r2g)     s[nt][2] = -1e30f;
                if (cg + 1 > r2g) s[nt][3] = -1e30f;
            }
        }

        // ---- online softmax (rows r1, r2; quad lanes share a row) ----
        float mi0 = -1e30f, mi1 = -1e30f;
#pragma unroll
        for (int nt = 0; nt < 8; ++nt) {
            mi0 = fmaxf(mi0, fmaxf(s[nt][0], s[nt][1]));
            mi1 = fmaxf(mi1, fmaxf(s[nt][2], s[nt][3]));
        }
        mi0 = fmaxf(mi0, __shfl_xor_sync(0xffffffffu, mi0, 1));
        mi0 = fmaxf(mi0, __shfl_xor_sync(0xffffffffu, mi0, 2));
        mi1 = fmaxf(mi1, __shfl_xor_sync(0xffffffffu, mi1, 1));
        mi1 = fmaxf(mi1, __shfl_xor_sync(0xffffffffu, mi1, 2));
        const float mn0 = fmaxf(m0, mi0), mn1 = fmaxf(m1, mi1);
        const float al0 = __expf(m0 - mn0), al1 = __expf(m1 - mn1);
        float rs0 = 0.0f, rs1 = 0.0f;
#pragma unroll
        for (int nt = 0; nt < 8; ++nt) {
            s[nt][0] = __expf(s[nt][0] - mn0);
            s[nt][1] = __expf(s[nt][1] - mn0);
            s[nt][2] = __expf(s[nt][2] - mn1);
            s[nt][3] = __expf(s[nt][3] - mn1);
            rs0 += s[nt][0] + s[nt][1];
            rs1 += s[nt][2] + s[nt][3];
        }
        rs0 += __shfl_xor_sync(0xffffffffu, rs0, 1);
        rs0 += __shfl_xor_sync(0xffffffffu, rs0, 2);
        rs1 += __shfl_xor_sync(0xffffffffu, rs1, 1);
        rs1 += __shfl_xor_sync(0xffffffffu, rs1, 2);
        l0 = l0 * al0 + rs0;
        l1 = l1 * al1 + rs1;
        m0 = mn0; m1 = mn1;
#pragma unroll
        for (int nt = 0; nt < 16; ++nt) {
            of[nt][0] *= al0; of[nt][1] *= al0;
            of[nt][2] *= al1; of[nt][3] *= al1;
        }

        // ---- O += P V  (P fragments packed directly from S) ----
#pragma unroll
        for (int kc = 0; kc < 4; ++kc) {
            uint32_t pH[4], pL[4];
            pack_hl(s[2 * kc][0],     s[2 * kc][1],     pH[0], pL[0]);
            pack_hl(s[2 * kc][2],     s[2 * kc][3],     pH[1], pL[1]);
            pack_hl(s[2 * kc + 1][0], s[2 * kc + 1][1], pH[2], pL[2]);
            pack_hl(s[2 * kc + 1][2], s[2 * kc + 1][3], pH[3], pL[3]);
#pragma unroll
            for (int np = 0; np < 8; ++np) {
                uint32_t vH[4], vL[4];
                int dd = np * 16 + (lane & 7) + ((lane >> 4) << 3);
                int c  = 2 * kc + ((lane >> 3) & 1);
                uint32_t sw = (uint32_t)(c ^ (dd & 7));
                uint32_t ad = kb + 32768 + dd * 128 + (sw << 4);
                LDSM4(vH, ad);
                LDSM4(vL, ad + 16384);
#pragma unroll
                for (int half = 0; half < 2; ++half) {
                    float* acc = of[np * 2 + half];
                    MMA16816(acc, pH, &vH[half * 2]);
                    MMA16816(acc, pH, &vL[half * 2]);
                    MMA16816(acc, pL, &vH[half * 2]);
                }
            }
        }

        if (kt + 1 < nkt) {
            CP_WAIT0();
            __syncthreads();
        }
    }

    // ---- normalize + write ----
    const float inv0 = 1.0f / l0, inv1 = 1.0f / l1;
    const int r1 = qbase + w * 16 + (lane >> 2);
#pragma unroll
    for (int nt = 0; nt < 16; ++nt) {
        const int d = h * DH + nt * 8 + 2 * (lane & 3);
        *(float2*)(g_AO + (size_t)(b * SEQ + r1) * HID + d) =
            make_float2(of[nt][0] * inv0, of[nt][1] * inv0);
        *(float2*)(g_AO + (size_t)(b * SEQ + r1 + 8) * HID + d) =
            make_float2(of[nt][2] * inv1, of[nt][3] * inv1);
    }
}

// =========================================================================
extern "C" void kernel_launch(void* const* d_in, const int* in_sizes, int n_in,
                              void* d_out, int out_size)
{
    const float* X  = (const float*)d_in[0];
    const float* Wq = (const float*)d_in[1];
    const float* Wk = (const float*)d_in[2];
    const float* Wv = (const float*)d_in[3];
    const float* Wo = (const float*)d_in[4];
    const int*  pos = (const int*)d_in[6];
    float* out = (float*)d_out;

    const int conv_blocks = (int)(((size_t)HID * HID / 4) / 256);   // 16384

    convert_split<<<conv_blocks, 256>>>(X,  0);
    convert_split<<<conv_blocks, 256>>>(Wq, 1);
    convert_split<<<conv_blocks, 256>>>(Wk, 2);
    convert_split<<<conv_blocks, 256>>>(Wv, 3);
    convert_split<<<conv_blocks, 256>>>(Wo, 4);

    cudaFuncSetAttribute(gemm_mma3,
                         cudaFuncAttributeMaxDynamicSharedMemorySize, GEMM_SMEM);
    gemm_mma3<<<dim3(HID / 128, MROWS / 128, 3), 256, GEMM_SMEM>>>(nullptr, 0);

    rope_split<<<dim3(MROWS, 2), 256>>>(pos);
    vsplit_t<<<dim3(SEQ / 64, NH * 2, BSZ), 256>>>();

    cudaFuncSetAttribute(flash_attn_mma,
                         cudaFuncAttributeMaxDynamicSharedMemorySize, ATTN_SMEM);
    flash_attn_mma<<<dim3(SEQ / 128, NH, BSZ), 256, ATTN_SMEM>>>();

    convert_split<<<conv_blocks, 256>>>(nullptr, 5);
    gemm_mma3<<<dim3(HID / 128, MROWS / 128, 1), 256, GEMM_SMEM>>>(out, 1);
}

// round 13
// speedup vs baseline: 3.6942x; 1.0015x over previous
#include <cuda_runtime.h>
#include <cuda_bf16.h>
#include <math.h>
#include <stdint.h>

typedef __nv_bfloat16 bf16;

#define BSZ   2
#define SEQ   2048
#define HID   4096
#define NH    32
#define DH    128
#define MROWS (BSZ * SEQ)

// ---------------- scratch (static device globals; no allocation allowed) ----
// bf16 hi/lo splits
__device__ bf16 g_Xh[(size_t)MROWS * HID],  g_Xl[(size_t)MROWS * HID];
__device__ bf16 g_AOh[(size_t)MROWS * HID], g_AOl[(size_t)MROWS * HID];
__device__ bf16 g_Wqh[(size_t)HID * HID], g_Wql[(size_t)HID * HID];
__device__ bf16 g_Wkh[(size_t)HID * HID], g_Wkl[(size_t)HID * HID];
__device__ bf16 g_Wvh[(size_t)HID * HID], g_Wvl[(size_t)HID * HID];
__device__ bf16 g_Woh[(size_t)HID * HID], g_Wol[(size_t)HID * HID];
// attention operand splits (Q/K roped+scaled; V transposed to [b,h,d,s])
__device__ bf16 g_Qbh[(size_t)MROWS * HID], g_Qbl[(size_t)MROWS * HID];
__device__ bf16 g_Kbh[(size_t)MROWS * HID], g_Kbl[(size_t)MROWS * HID];
__device__ bf16 g_Vth[(size_t)MROWS * HID], g_Vtl[(size_t)MROWS * HID];

// ---------------- PTX helpers (all sm_80-class; no 'a'-gated features) -----
__device__ __forceinline__ uint32_t cvta_s(const void* p) {
    return (uint32_t)__cvta_generic_to_shared(p);
}
#define CP_ASYNC16(saddr, gptr) \
    asm volatile("cp.async.cg.shared.global [%0], [%1], 16;" \
                 :: "r"(saddr), "l"(gptr))
#define CP_COMMIT() asm volatile("cp.async.commit_group;")
#define CP_WAIT0()  asm volatile("cp.async.wait_group 0;")

#define LDSM4(r, addr) \
    asm volatile("ldmatrix.sync.aligned.m8n8.x4.shared.b16 {%0,%1,%2,%3}, [%4];" \
                 : "=r"((r)[0]), "=r"((r)[1]), "=r"((r)[2]), "=r"((r)[3]) \
                 : "r"(addr))

#define MMA16816(d, a, b) \
    asm volatile("mma.sync.aligned.m16n8k16.row.col.f32.bf16.bf16.f32 " \
                 "{%0,%1,%2,%3}, {%4,%5,%6,%7}, {%8,%9}, {%0,%1,%2,%3};" \
                 : "+f"((d)[0]), "+f"((d)[1]), "+f"((d)[2]), "+f"((d)[3]) \
                 : "r"((a)[0]), "r"((a)[1]), "r"((a)[2]), "r"((a)[3]), \
                   "r"((b)[0]), "r"((b)[1]))

__device__ __forceinline__ void split_hl(float a, bf16& h, bf16& l) {
    h = __float2bfloat16(a);
    l = __float2bfloat16(a - __bfloat162float(h));
}
__device__ __forceinline__ void pack_hl(float a, float b,
                                        uint32_t& hi, uint32_t& lo) {
    bf16 ha, la, hb, lb;
    split_hl(a, ha, la);
    split_hl(b, hb, lb);
    __nv_bfloat162 hp; hp.x = ha; hp.y = hb;
    __nv_bfloat162 lp; lp.x = la; lp.y = lb;
    hi = *(uint32_t*)&hp;
    lo = *(uint32_t*)&lp;
}

// =========================================================================
// split-to-bf16 conversion:  hi = bf16(x), lo = bf16(x - hi)
// dst_sel: 0=X 1=Wq 2=Wk 3=Wv 4=Wo
// =========================================================================
__global__ __launch_bounds__(256) void convert_split(const float* __restrict__ src,
                                                     int dst_sel) {
    bf16 *hi, *lo;
    switch (dst_sel) {
        case 1: hi = g_Wqh; lo = g_Wql; break;
        case 2: hi = g_Wkh; lo = g_Wkl; break;
        case 3: hi = g_Wvh; lo = g_Wvl; break;
        case 4: hi = g_Woh; lo = g_Wol; break;
        default: hi = g_Xh;  lo = g_Xl;  break;
    }
    size_t i = (size_t)blockIdx.x * blockDim.x + threadIdx.x;  // float4 index
    float4 v = ((const float4*)src)[i];
    uint32_t h0, l0, h1, l1;
    pack_hl(v.x, v.y, h0, l0);
    pack_hl(v.z, v.w, h1, l1);
    ((uint32_t*)hi)[i * 2]     = h0;
    ((uint32_t*)hi)[i * 2 + 1] = h1;
    ((uint32_t*)lo)[i * 2]     = l0;
    ((uint32_t*)lo)[i * 2 + 1] = l1;
}

// =========================================================================
// mma.sync bf16 3-term GEMM:  C[m,n] = sum_k A[m,k] * W[n,k]
// mode 0: A = X splits, W by blockIdx.z (Q/K/V). Epilogue FUSES:
//   z<2 : RoPE + scale + bf16 split -> g_Qb*/g_Kb*
//   z==2: transpose + bf16 split    -> g_Vt*  ([b,h,d,s])
// mode 1: A = AO splits x Wo -> fp32 Cext (harness output)
// =========================================================================
#define TILE_B   16384
#define BUF_B    65536
#define GEMM_SMEM (2 * BUF_B)
#define NCHUNK   64
#define FST      129      // fp32 staging stride (odd -> low smem conflicts)

__global__ __launch_bounds__(256, 1) void gemm_mma3(float* __restrict__ Cext,
                                                    int mode,
                                                    const int* __restrict__ pos) {
    extern __shared__ char dsm[];
    const uint32_t sb = cvta_s(dsm);
    __shared__ float s_inv[64];

    const int z = blockIdx.z;
    const bf16 *Ah, *Al, *Wh, *Wl;
    if (mode == 0) {
        Ah = g_Xh; Al = g_Xl;
        Wh = (z == 0) ? g_Wqh : (z == 1) ? g_Wkh : g_Wvh;
        Wl = (z == 0) ? g_Wql : (z == 1) ? g_Wkl : g_Wvl;
        if (z < 2 && threadIdx.x < 64)
            s_inv[threadIdx.x] =
                (float)exp(-(double)threadIdx.x * (2.0 / (double)DH) * log(10000.0));
    } else {
        Ah = g_AOh; Al = g_AOl; Wh = g_Woh; Wl = g_Wol;
    }

    const int t    = threadIdx.x;
    const int lane = t & 31;
    const int wid  = t >> 5;
    const int wm   = wid >> 2;
    const int wn   = wid & 3;
    const int bm   = blockIdx.y * 128;
    const int bn   = blockIdx.x * 128;

    const int lxor = lane & 7;
    uint32_t aRow[4], bRow[2];
#pragma unroll
    for (int mt = 0; mt < 4; ++mt)
        aRow[mt] = (uint32_t)((wm * 64 + mt * 16 + (lane & 15)) * 128);
#pragma unroll
    for (int np = 0; np < 2; ++np)
        bRow[np] = (uint32_t)((wn * 32 + np * 16 + (lane & 7) + ((lane & 16) >> 1)) * 128);
    const int uA = lane >> 4;
    const int uB = (lane >> 3) & 1;

    auto load_chunk = [&](int buf, int k0) {
        const bf16* srcs[4] = {Ah, Al, Wh, Wl};
#pragma unroll
        for (int tile = 0; tile < 4; ++tile) {
            const int rowbase = (tile < 2) ? bm : bn;
            const bf16* src = srcs[tile];
#pragma unroll
            for (int i = 0; i < 4; ++i) {
                int idx = t + i * 256;
                int r = idx >> 3, u = idx & 7;
                uint32_t soff = (uint32_t)(buf * BUF_B + tile * TILE_B
                                           + r * 128 + ((u ^ (r & 7)) << 4));
                const bf16* g = src + (size_t)(rowbase + r) * HID + k0 + u * 8;
                CP_ASYNC16(sb + soff, g);
            }
        }
    };

    float acc[4][4][4];
#pragma unroll
    for (int mt = 0; mt < 4; ++mt)
#pragma unroll
        for (int nt = 0; nt < 4; ++nt)
#pragma unroll
            for (int j = 0; j < 4; ++j) acc[mt][nt][j] = 0.0f;

    load_chunk(0, 0);
    CP_COMMIT();
    CP_WAIT0();
    __syncthreads();

    for (int c = 0; c < NCHUNK; ++c) {
        const int buf = c & 1;
        if (c + 1 < NCHUNK) {
            load_chunk(buf ^ 1, (c + 1) * 64);
            CP_COMMIT();
        }

        const uint32_t base = sb + buf * BUF_B;
#pragma unroll
        for (int ks = 0; ks < 4; ++ks) {
            const uint32_t offA = (uint32_t)((((2 * ks + uA) ^ lxor)) << 4);
            const uint32_t offB = (uint32_t)((((2 * ks + uB) ^ lxor)) << 4);
            uint32_t ah[4][4], al[4][4], bh[2][4], bl[2][4];
#pragma unroll
            for (int mt = 0; mt < 4; ++mt) {
                LDSM4(ah[mt], base + 0 * TILE_B + aRow[mt] + offA);
                LDSM4(al[mt], base + 1 * TILE_B + aRow[mt] + offA);
            }
#pragma unroll
            for (int np = 0; np < 2; ++np) {
                LDSM4(bh[np], base + 2 * TILE_B + bRow[np] + offB);
                LDSM4(bl[np], base + 3 * TILE_B + bRow[np] + offB);
            }
#pragma unroll
            for (int mt = 0; mt < 4; ++mt)
#pragma unroll
                for (int nt = 0; nt < 4; ++nt) {
                    const uint32_t* bhp = &bh[nt >> 1][(nt & 1) * 2];
                    const uint32_t* blp = &bl[nt >> 1][(nt & 1) * 2];
                    MMA16816(acc[mt][nt], ah[mt], bhp);
                    MMA16816(acc[mt][nt], ah[mt], blp);
                    MMA16816(acc[mt][nt], al[mt], bhp);
                }
        }

        if (c + 1 < NCHUNK) {
            CP_WAIT0();
            __syncthreads();
        }
    }

    const int g  = lane >> 2;
    const int tq = lane & 3;

    if (mode == 1) {
        // ---- plain fp32 epilogue (harness output) ----
#pragma unroll
        for (int mt = 0; mt < 4; ++mt) {
            const int row0 = bm + wm * 64 + mt * 16 + g;
#pragma unroll
            for (int nt = 0; nt < 4; ++nt) {
                const int col = bn + wn * 32 + nt * 8 + tq * 2;
                *(float2*)(Cext + (size_t)row0 * HID + col) =
                    make_float2(acc[mt][nt][0], acc[mt][nt][1]);
                *(float2*)(Cext + (size_t)(row0 + 8) * HID + col) =
                    make_float2(acc[mt][nt][2], acc[mt][nt][3]);
            }
        }
        return;
    }

    // ---- fused epilogue: stage fp32 tile to smem, then rope/transpose+split
    __syncthreads();                     // all ldsm of last chunk done
    float* fsm = (float*)dsm;            // 128 x FST fp32 tile (66 KB)
#pragma unroll
    for (int mt = 0; mt < 4; ++mt) {
        const int r0 = wm * 64 + mt * 16 + g;
#pragma unroll
        for (int nt = 0; nt < 4; ++nt) {
            const int cc = wn * 32 + nt * 8 + tq * 2;
            fsm[r0 * FST + cc]           = acc[mt][nt][0];
            fsm[r0 * FST + cc + 1]       = acc[mt][nt][1];
            fsm[(r0 + 8) * FST + cc]     = acc[mt][nt][2];
            fsm[(r0 + 8) * FST + cc + 1] = acc[mt][nt][3];
        }
    }
    __syncthreads();

    if (z < 2) {
        // ---- RoPE + scale + split (Q gets 1/sqrt(Dh)) ----
        const bool isQ = (z == 0);
        const float sc = isQ ? 0.08838834764831845f : 1.0f;
        bf16* hi = isQ ? g_Qbh : g_Kbh;
        bf16* lo = isQ ? g_Qbl : g_Kbl;
#pragma unroll
        for (int it = 0; it < 32; ++it) {
            int pi = t + it * 256;           // 0..8191
            int r  = pi >> 6;                // 0..127
            int j  = pi & 63;
            float x1 = fsm[r * FST + j];
            float x2 = fsm[r * FST + j + 64];
            int s = (bm + r) & (SEQ - 1);
            float p = (float)pos[s];
            float sn, cs;
            sincosf(p * s_inv[j], &sn, &cs);
            float y1 = (x1 * cs - x2 * sn) * sc;
            float y2 = (x2 * cs + x1 * sn) * sc;
            bf16 h1, l1, h2, l2;
            split_hl(y1, h1, l1);
            split_hl(y2, h2, l2);
            size_t o = (size_t)(bm + r) * HID + bn + j;
            hi[o] = h1;       lo[o] = l1;
            hi[o + 64] = h2;  lo[o + 64] = l2;
        }
    } else {
        // ---- V: transpose + split -> [b,h,d,s] ----
        const int hh = bn >> 7;
        const int bb = bm >> 11;             // SEQ = 2048
        const int sbase = bm & (SEQ - 1);
#pragma unroll
        for (int it = 0; it < 32; ++it) {
            int idx = t + it * 256;          // 0..8191
            int d  = idx >> 6;               // 0..127
            int s2 = (idx & 63) * 2;         // 0..126 even
            float v0 = fsm[s2 * FST + d];
            float v1 = fsm[(s2 + 1) * FST + d];
            uint32_t hv, lv;
            pack_hl(v0, v1, hv, lv);
            size_t o = ((size_t)((bb * NH + hh) * DH + d)) * SEQ + sbase + s2;
            *(uint32_t*)(g_Vth + o) = hv;
            *(uint32_t*)(g_Vtl + o) = lv;
        }
    }
}

// =========================================================================
// Causal flash attention on mma.sync bf16x3.
// grid = (SEQ/128, NH, BSZ), 256 threads (8 warps; warp w owns rows w*16..+15).
// Epilogue writes bf16 hi/lo splits of AO directly (feeds O-proj GEMM).
// =========================================================================
#define ATQ_B  32768                       // one 128x128 bf16 Q split
#define KV_B   65536                       // one KV buffer (4 x 16KB)
#define ATTN_SMEM (2 * ATQ_B + 2 * KV_B)   // 196608

__global__ __launch_bounds__(256, 1) void flash_attn_mma()
{
    extern __shared__ char sm[];
    const uint32_t sb = cvta_s(sm);
    const int qt = blockIdx.x, h = blockIdx.y, b = blockIdx.z;
    const int qbase = qt * 128;
    const int t = threadIdx.x, lane = t & 31, w = t >> 5;

    // ---- load Q tile (both splits), swizzled 16B chunks ----
    {
        const bf16* srcs[2] = {g_Qbh, g_Qbl};
#pragma unroll
        for (int sp = 0; sp < 2; ++sp) {
            const bf16* src = srcs[sp];
#pragma unroll
            for (int i = 0; i < 8; ++i) {
                int idx = t + i * 256;       // 0..2047
                int r = idx >> 4, u = idx & 15;
                uint32_t sw = (uint32_t)(((u & 7) ^ (r & 7)) | (u & 8));
                const bf16* g = src + (size_t)(b * SEQ + qbase + r) * HID
                                    + h * DH + u * 8;
                CP_ASYNC16(sb + sp * ATQ_B + r * 256 + (sw << 4), g);
            }
        }
    }

    auto load_kv = [&](int buf, int kt) {
        const uint32_t off = 2 * ATQ_B + buf * KV_B;
        const int kbase = kt * 64;
#pragma unroll
        for (int i = 0; i < 4; ++i) {
            int idx = t + i * 256;           // 0..1023
            int r = idx >> 4, u = idx & 15;
            uint32_t sw = (uint32_t)(((u & 7) ^ (r & 7)) | (u & 8));
            size_t gi = (size_t)(b * SEQ + kbase + r) * HID + h * DH + u * 8;
            CP_ASYNC16(sb + off + r * 256 + (sw << 4), g_Kbh + gi);
            CP_ASYNC16(sb + off + 16384 + r * 256 + (sw << 4), g_Kbl + gi);
        }
#pragma unroll
        for (int i = 0; i < 4; ++i) {
            int idx = t + i * 256;           // 0..1023
            int d = idx >> 3, u = idx & 7;
            uint32_t sw = (uint32_t)(u ^ (d & 7));
            size_t gi = (size_t)((b * NH + h) * DH + d) * SEQ + kbase + u * 8;
            CP_ASYNC16(sb + off + 32768 + d * 128 + (sw << 4), g_Vth + gi);
            CP_ASYNC16(sb + off + 49152 + d * 128 + (sw << 4), g_Vtl + gi);
        }
    };

    load_kv(0, 0);
    CP_COMMIT();
    CP_WAIT0();
    __syncthreads();

    float of[16][4];
#pragma unroll
    for (int nt = 0; nt < 16; ++nt)
#pragma unroll
        for (int j = 0; j < 4; ++j) of[nt][j] = 0.0f;
    float m0 = -1e30f, m1 = -1e30f, l0 = 0.0f, l1 = 0.0f;

    const int nkt = 2 * (qt + 1);
    for (int kt = 0; kt < nkt; ++kt) {
        const int buf = kt & 1;
        if (kt + 1 < nkt) {
            load_kv(buf ^ 1, kt + 1);
            CP_COMMIT();
        }
        const uint32_t kb = sb + 2 * ATQ_B + buf * KV_B;

        // ---- S = Q K^T  (128x64 tile; this warp: 16x64) ----
        float s[8][4];
#pragma unroll
        for (int nt = 0; nt < 8; ++nt)
#pragma unroll
            for (int j = 0; j < 4; ++j) s[nt][j] = 0.0f;

#pragma unroll
        for (int ks = 0; ks < 8; ++ks) {
            uint32_t aH[4], aL[4];
            {
                int r = w * 16 + (lane & 15);
                int c = 2 * ks + (lane >> 4);
                uint32_t sw = (uint32_t)(((c & 7) ^ (r & 7)) | (c & 8));
                uint32_t ad = sb + r * 256 + (sw << 4);
                LDSM4(aH, ad);
                LDSM4(aL, ad + ATQ_B);
            }
#pragma unroll
            for (int np = 0; np < 4; ++np) {
                uint32_t bH[4], bL[4];
                int rr = np * 16 + (lane & 7) + ((lane >> 4) << 3);
                int c  = 2 * ks + ((lane >> 3) & 1);
                uint32_t sw = (uint32_t)(((c & 7) ^ (rr & 7)) | (c & 8));
                uint32_t ad = kb + rr * 256 + (sw << 4);
                LDSM4(bH, ad);
                LDSM4(bL, ad + 16384);
#pragma unroll
                for (int half = 0; half < 2; ++half) {
                    float* acc = s[np * 2 + half];
                    MMA16816(acc, aH, &bH[half * 2]);
                    MMA16816(acc, aH, &bL[half * 2]);
                    MMA16816(acc, aL, &bH[half * 2]);
                }
            }
        }

        // ---- causal mask ----
        const int kbase = kt * 64;
        const int r1g = qbase + w * 16 + (lane >> 2);
        if (kbase + 63 > r1g) {
            const int r2g = r1g + 8;
#pragma unroll
            for (int nt = 0; nt < 8; ++nt) {
                int cg = kbase + nt * 8 + 2 * (lane & 3);
                if (cg > r1g)     s[nt][0] = -1e30f;
                if (cg + 1 > r1g) s[nt][1] = -1e30f;
                if (cg > r2g)     s[nt][2] = -1e30f;
                if (cg + 1 > r2g) s[nt][3] = -1e30f;
            }
        }

        // ---- online softmax (rows r1, r2; quad lanes share a row) ----
        float mi0 = -1e30f, mi1 = -1e30f;
#pragma unroll
        for (int nt = 0; nt < 8; ++nt) {
            mi0 = fmaxf(mi0, fmaxf(s[nt][0], s[nt][1]));
            mi1 = fmaxf(mi1, fmaxf(s[nt][2], s[nt][3]));
        }
        mi0 = fmaxf(mi0, __shfl_xor_sync(0xffffffffu, mi0, 1));
        mi0 = fmaxf(mi0, __shfl_xor_sync(0xffffffffu, mi0, 2));
        mi1 = fmaxf(mi1, __shfl_xor_sync(0xffffffffu, mi1, 1));
        mi1 = fmaxf(mi1, __shfl_xor_sync(0xffffffffu, mi1, 2));
        const float mn0 = fmaxf(m0, mi0), mn1 = fmaxf(m1, mi1);
        const float al0 = __expf(m0 - mn0), al1 = __expf(m1 - mn1);
        float rs0 = 0.0f, rs1 = 0.0f;
#pragma unroll
        for (int nt = 0; nt < 8; ++nt) {
            s[nt][0] = __expf(s[nt][0] - mn0);
            s[nt][1] = __expf(s[nt][1] - mn0);
            s[nt][2] = __expf(s[nt][2] - mn1);
            s[nt][3] = __expf(s[nt][3] - mn1);
            rs0 += s[nt][0] + s[nt][1];
            rs1 += s[nt][2] + s[nt][3];
        }
        rs0 += __shfl_xor_sync(0xffffffffu, rs0, 1);
        rs0 += __shfl_xor_sync(0xffffffffu, rs0, 2);
        rs1 += __shfl_xor_sync(0xffffffffu, rs1, 1);
        rs1 += __shfl_xor_sync(0xffffffffu, rs1, 2);
        l0 = l0 * al0 + rs0;
        l1 = l1 * al1 + rs1;
        m0 = mn0; m1 = mn1;
#pragma unroll
        for (int nt = 0; nt < 16; ++nt) {
            of[nt][0] *= al0; of[nt][1] *= al0;
            of[nt][2] *= al1; of[nt][3] *= al1;
        }

        // ---- O += P V  (P fragments packed directly from S) ----
#pragma unroll
        for (int kc = 0; kc < 4; ++kc) {
            uint32_t pH[4], pL[4];
            pack_hl(s[2 * kc][0],     s[2 * kc][1],     pH[0], pL[0]);
            pack_hl(s[2 * kc][2],     s[2 * kc][3],     pH[1], pL[1]);
            pack_hl(s[2 * kc + 1][0], s[2 * kc + 1][1], pH[2], pL[2]);
            pack_hl(s[2 * kc + 1][2], s[2 * kc + 1][3], pH[3], pL[3]);
#pragma unroll
            for (int np = 0; np < 8; ++np) {
                uint32_t vH[4], vL[4];
                int dd = np * 16 + (lane & 7) + ((lane >> 4) << 3);
                int c  = 2 * kc + ((lane >> 3) & 1);
                uint32_t sw = (uint32_t)(c ^ (dd & 7));
                uint32_t ad = kb + 32768 + dd * 128 + (sw << 4);
                LDSM4(vH, ad);
                LDSM4(vL, ad + 16384);
#pragma unroll
                for (int half = 0; half < 2; ++half) {
                    float* acc = of[np * 2 + half];
                    MMA16816(acc, pH, &vH[half * 2]);
                    MMA16816(acc, pH, &vL[half * 2]);
                    MMA16816(acc, pL, &vH[half * 2]);
                }
            }
        }

        if (kt + 1 < nkt) {
            CP_WAIT0();
            __syncthreads();
        }
    }

    // ---- normalize + write bf16 hi/lo splits directly ----
    const float inv0 = 1.0f / l0, inv1 = 1.0f / l1;
    const int r1 = qbase + w * 16 + (lane >> 2);
#pragma unroll
    for (int nt = 0; nt < 16; ++nt) {
        const int d = h * DH + nt * 8 + 2 * (lane & 3);
        const size_t o1 = (size_t)(b * SEQ + r1) * HID + d;
        const size_t o2 = (size_t)(b * SEQ + r1 + 8) * HID + d;
        uint32_t hv, lv;
        pack_hl(of[nt][0] * inv0, of[nt][1] * inv0, hv, lv);
        *(uint32_t*)(g_AOh + o1) = hv;
        *(uint32_t*)(g_AOl + o1) = lv;
        pack_hl(of[nt][2] * inv1, of[nt][3] * inv1, hv, lv);
        *(uint32_t*)(g_AOh + o2) = hv;
        *(uint32_t*)(g_AOl + o2) = lv;
    }
}

// =========================================================================
extern "C" void kernel_launch(void* const* d_in, const int* in_sizes, int n_in,
                              void* d_out, int out_size)
{
    const float* X  = (const float*)d_in[0];
    const float* Wq = (const float*)d_in[1];
    const float* Wk = (const float*)d_in[2];
    const float* Wv = (const float*)d_in[3];
    const float* Wo = (const float*)d_in[4];
    const int*  pos = (const int*)d_in[6];
    float* out = (float*)d_out;

    const int conv_blocks = (int)(((size_t)HID * HID / 4) / 256);   // 16384

    convert_split<<<conv_blocks, 256>>>(X,  0);
    convert_split<<<conv_blocks, 256>>>(Wq, 1);
    convert_split<<<conv_blocks, 256>>>(Wk, 2);
    convert_split<<<conv_blocks, 256>>>(Wv, 3);
    convert_split<<<conv_blocks, 256>>>(Wo, 4);

    cudaFuncSetAttribute(gemm_mma3,
                         cudaFuncAttributeMaxDynamicSharedMemorySize, GEMM_SMEM);
    gemm_mma3<<<dim3(HID / 128, MROWS / 128, 3), 256, GEMM_SMEM>>>(nullptr, 0, pos);

    cudaFuncSetAttribute(flash_attn_mma,
                         cudaFuncAttributeMaxDynamicSharedMemorySize, ATTN_SMEM);
    flash_attn_mma<<<dim3(SEQ / 128, NH, BSZ), 256, ATTN_SMEM>>>();

    gemm_mma3<<<dim3(HID / 128, MROWS / 128, 1), 256, GEMM_SMEM>>>(out, 1, pos);
}